// round 7
// baseline (speedup 1.0000x reference)
#include <cuda_runtime.h>
#include <cuda_bf16.h>
#include <cstdint>

#define Bn   8
#define Cn   256
#define Kn   9
#define Hn   64
#define Wn   64
#define HWn  (Hn*Wn)       // 4096
#define NPIX (Bn*HWn)      // 32768
#define JMAX 40

// ---- scratch (device globals; no allocation allowed) ----
__device__ float g_key_t[(size_t)Bn*HWn*Cn];          // [B][HW][C] transposed key
__device__ __nv_bfloat16 g_sh[(size_t)NPIX*Cn];       // sampled features, bf16 hi
__device__ __nv_bfloat16 g_sl[(size_t)NPIX*Cn];       // sampled features, bf16 lo
__device__ __nv_bfloat16 g_wh[Cn*Cn];                 // w_refer hi
__device__ __nv_bfloat16 g_wl[Cn*Cn];                 // w_refer lo
__device__ float g_g[NPIX];                            // bias weight-sum per pixel
__device__ float g_tapw[JMAX*NPIX];                    // tap weights  [j][pix]
__device__ int   g_tapidx[JMAX*NPIX];                  // tap hw index [j][pix]
__device__ int   g_tapn[NPIX];                         // tap counts

// ================= helpers =================
__device__ __forceinline__ uint32_t smem_u32(const void* p) {
    uint32_t a;
    asm("{ .reg .u64 t; cvta.to.shared.u64 t, %1; cvt.u32.u64 %0, t; }" : "=r"(a) : "l"(p));
    return a;
}
__device__ __forceinline__ uint32_t lds32(uint32_t a) {
    uint32_t v;
    asm volatile("ld.shared.b32 %0, [%1];" : "=r"(v) : "r"(a));
    return v;
}
__device__ __forceinline__ void ldmatrix_x4(uint32_t& r0, uint32_t& r1,
                                            uint32_t& r2, uint32_t& r3, uint32_t a) {
    asm volatile("ldmatrix.sync.aligned.m8n8.x4.shared.b16 {%0,%1,%2,%3}, [%4];"
                 : "=r"(r0), "=r"(r1), "=r"(r2), "=r"(r3) : "r"(a));
}
__device__ __forceinline__ void mma16816(float* c, uint32_t a0, uint32_t a1,
                                         uint32_t a2, uint32_t a3,
                                         uint32_t b0, uint32_t b1) {
    asm volatile(
        "mma.sync.aligned.m16n8k16.row.col.f32.bf16.bf16.f32 "
        "{%0,%1,%2,%3}, {%4,%5,%6,%7}, {%8,%9}, {%0,%1,%2,%3};"
        : "+f"(c[0]), "+f"(c[1]), "+f"(c[2]), "+f"(c[3])
        : "r"(a0), "r"(a1), "r"(a2), "r"(a3), "r"(b0), "r"(b1));
}
__device__ __forceinline__ void cp16(uint32_t s, const void* g) {
    asm volatile("cp.async.cg.shared.global [%0], [%1], 16;" :: "r"(s), "l"(g));
}
__device__ __forceinline__ void cp_commit() {
    asm volatile("cp.async.commit_group;" ::: "memory");
}
template<int N> __device__ __forceinline__ void cp_wait() {
    asm volatile("cp.async.wait_group %0;" :: "n"(N) : "memory");
}

// ============================================================
// K1: transpose key_layer [B,C,HW] -> g_key_t [B,HW,C]
// ============================================================
__global__ void k_transpose(const float* __restrict__ key) {
    __shared__ float t[32][33];
    int b   = blockIdx.z;
    int hw0 = blockIdx.x * 32;
    int c0  = blockIdx.y * 32;
    int tx = threadIdx.x, ty = threadIdx.y;
    const float* src = key + (size_t)b * Cn * HWn;
    #pragma unroll
    for (int i = 0; i < 4; i++)
        t[ty + i*8][tx] = src[(size_t)(c0 + ty + i*8) * HWn + hw0 + tx];
    __syncthreads();
    float* dst = g_key_t + (size_t)b * HWn * Cn;
    #pragma unroll
    for (int i = 0; i < 4; i++)
        dst[(size_t)(hw0 + ty + i*8) * Cn + c0 + tx] = t[tx][ty + i*8];
}

// ============================================================
// K2: per-pixel params + softmaxes + TAP LIST BUILD.
// Block = 128 pixels, 256 threads, split-C reduction.
// SMEM phase A: sW | sB | sPart ; phase B (overlay): tap lists.
// ============================================================
__global__ void __launch_bounds__(256)
k_params(const float* __restrict__ query,
         const float* __restrict__ gmb,
         const float* __restrict__ b_attn,
         const float* __restrict__ b_mask,
         const float* __restrict__ b_off,
         const float* __restrict__ w_attn,
         const float* __restrict__ w_mask,
         const float* __restrict__ w_off,
         const unsigned* __restrict__ temp_raw) {
    __shared__ __align__(16) char sm[44032];
    float4* sW    = (float4*)sm;             // 28672 B
    float*  sB    = (float*)(sm + 28672);    // 128 B
    float*  sPart = (float*)(sm + 28800);    // 128*29*4 = 14848 B
    // overlay (after phase A):
    float*  s_tw  = (float*)sm;              // 128*41*4 = 20992 B
    int*    s_ti  = (int*)(sm + 20992);      // 20992 B

    int tid = threadIdx.x;
    for (int i = tid; i < 576; i += 256) sW[i]        = ((const float4*)w_attn)[i];
    for (int i = tid; i < 576; i += 256) sW[576 + i]  = ((const float4*)w_mask)[i];
    for (int i = tid; i < 640; i += 256) sW[1152 + i] = ((const float4*)w_off)[i];
    if (tid < 9)  { sB[tid] = b_attn[tid]; sB[9 + tid] = b_mask[tid]; }
    if (tid < 10) sB[18 + tid] = b_off[tid];
    __syncthreads();

    int lp = tid & 127, ph = tid >> 7;
    int pix = blockIdx.x * 128 + lp;
    int b  = pix >> 12;
    int hw = pix & (HWn - 1);

    const float* q = query + (size_t)b * Cn * HWn + (size_t)(ph*128) * HWn + hw;
    float acc[28];
    #pragma unroll
    for (int r = 0; r < 28; r++) acc[r] = 0.f;

    #pragma unroll 4
    for (int c4 = 0; c4 < 32; c4++) {
        float q0 = q[(c4*4 + 0) * HWn];
        float q1 = q[(c4*4 + 1) * HWn];
        float q2 = q[(c4*4 + 2) * HWn];
        float q3 = q[(c4*4 + 3) * HWn];
        #pragma unroll
        for (int r = 0; r < 28; r++) {
            float4 w = sW[r*64 + ph*32 + c4];
            acc[r] += q0*w.x + q1*w.y + q2*w.z + q3*w.w;
        }
    }

    if (ph == 1) {
        #pragma unroll
        for (int r = 0; r < 28; r++) sPart[lp*29 + r] = acc[r];
    }
    __syncthreads();

    float aw9[9], dy9[9], dx9[9];
    if (ph == 0) {
        #pragma unroll
        for (int r = 0; r < 28; r++) acc[r] += sPart[lp*29 + r];

        unsigned lo = temp_raw[0];
        float t;
        if      (lo == 1u)           t = 1.f;
        else if (lo == 0x3F800000u)  t = 1.f;
        else if (lo == 0u)           t = 1.f;
        else                         t = __uint_as_float(lo);
        float invt = 1.f / t;

        float mv[9]; float mx = -3.4e38f;
        #pragma unroll
        for (int k = 0; k < 9; k++) {
            float gk = gmb[(size_t)(b*Kn + k) * HWn + hw];
            mv[k] = (acc[9 + k] + sB[9 + k] + gk) * invt;
            mx = fmaxf(mx, mv[k]);
        }
        float sum = 0.f;
        #pragma unroll
        for (int k = 0; k < 9; k++) { mv[k] = expf(mv[k] - mx); sum += mv[k]; }
        float rs = 1.f / sum;

        float z[9]; float mx2 = -3.4e38f;
        #pragma unroll
        for (int k = 0; k < 9; k++) {
            z[k] = (acc[k] + sB[k]) * (mv[k] * rs);
            mx2 = fmaxf(mx2, z[k]);
        }
        float sum2 = 0.f;
        #pragma unroll
        for (int k = 0; k < 9; k++) { z[k] = expf(z[k] - mx2); sum2 += z[k]; }
        float rs2 = 1.f / sum2;

        #pragma unroll
        for (int k = 0; k < 9; k++) {
            aw9[k] = z[k] * rs2;
            dy9[k] = acc[18 + k] + sB[18 + k];
            dx9[k] = acc[19 + k] + sB[19 + k];
        }
    }
    __syncthreads();   // done with sW/sB/sPart -> overlay

    if (ph == 0) {
        int py0 = hw >> 6, px0 = hw & 63;
        float gs = 0.f; int n = 0;
        #pragma unroll
        for (int k = 0; k < 9; k++) {
            float aw = aw9[k];
            float py = (float)py0 + dy9[k];
            float px = (float)px0 + dx9[k];
            float y0f = floorf(py), x0f = floorf(px);
            float wy = py - y0f, wx = px - x0f;
            int y0 = (int)y0f, x0 = (int)x0f;
            float ws[4] = {(1.f-wy)*(1.f-wx), (1.f-wy)*wx, wy*(1.f-wx), wy*wx};
            int   yy[4] = {y0, y0, y0+1, y0+1};
            int   xx[4] = {x0, x0+1, x0, x0+1};
            #pragma unroll
            for (int t4 = 0; t4 < 4; t4++) {
                bool v = (yy[t4] >= 0) & (yy[t4] < Hn) & (xx[t4] >= 0) & (xx[t4] < Wn);
                float w = ws[t4] * aw;
                if (!v || w == 0.f) continue;
                int idx = yy[t4]*Wn + xx[t4];
                gs += w;
                int j = 0;
                for (; j < n; j++)
                    if (s_ti[lp*41 + j] == idx) { s_tw[lp*41 + j] += w; break; }
                if (j == n && n < JMAX) { s_ti[lp*41 + n] = idx; s_tw[lp*41 + n] = w; n++; }
            }
        }
        g_g[pix] = gs;
        g_tapn[pix] = n;
        for (int j = 0; j < n; j++) {
            g_tapw[j*NPIX + pix]   = s_tw[lp*41 + j];
            g_tapidx[j*NPIX + pix] = s_ti[lp*41 + j];
        }
    }
}

// ============================================================
// K3: split w_refer into bf16 hi/lo
// ============================================================
__global__ void k_wsplit(const float* __restrict__ w) {
    int i = blockIdx.x * 256 + threadIdx.x;
    float v = w[i];
    __nv_bfloat16 h = __float2bfloat16(v);
    g_wh[i] = h;
    g_wl[i] = __float2bfloat16(v - __bfloat162float(h));
}

// ============================================================
// K4: gather. Block = (row y, batch b, channel-quarter cq).
// Stage 3-row x 64-col x 64-ch window in SMEM; taps read via LDS.
// Far taps (|dy|>=1, rare) read global with flag bit 30.
// ============================================================
#define WIN_F   (3*64*64)                    // 12288 floats = 49152 B
#define GATHER_SMEM (49152 + 64*JMAX*4*2 + 32)  // win + tw + toff + nmax

__global__ void __launch_bounds__(256)
k_gather() {
    extern __shared__ __align__(16) char gsm[];
    float* win  = (float*)gsm;                       // 49152 B
    float* stw  = (float*)(gsm + 49152);             // 64*JMAX floats
    int*   sto  = (int*)(gsm + 49152 + 64*JMAX*4);   // 64*JMAX ints
    int*   snmx = (int*)(gsm + 49152 + 64*JMAX*8);

    int y  = blockIdx.x;
    int b  = blockIdx.y;
    int cq = blockIdx.z;
    int tid = threadIdx.x;
    int ytop = y - 1;

    if (tid == 0) *snmx = 0;
    // zero-fill tap arrays (padding -> w=0, off=safe slot 1 = row y, col 0)
    for (int i = tid; i < 64*JMAX; i += 256) { stw[i] = 0.f; sto[i] = 4096; }
    __syncthreads();

    // stage window rows
    const float* kb = g_key_t + (size_t)b * HWn * Cn;
    #pragma unroll
    for (int s = 0; s < 3; s++) {
        int r = ytop + s;
        if (r >= 0 && r < Hn) {
            for (int i = tid; i < 1024; i += 256) {     // 1024 float4 = 16 KB
                int x = i >> 4, c4i = i & 15;
                ((float4*)win)[s*1024 + i] =
                    *(const float4*)&kb[(size_t)(r*Wn + x)*Cn + cq*64 + c4i*4];
            }
        }
    }

    // load tap lists (4 threads per pixel)
    {
        int p = tid >> 2, q = tid & 3;
        int pix = b*HWn + y*Wn + p;
        int n = g_tapn[pix];
        for (int j = q; j < n; j += 4) {
            float w = g_tapw[j*NPIX + pix];
            int hwt = g_tapidx[j*NPIX + pix];
            int r = hwt >> 6, x = hwt & 63;
            int s = r - ytop;
            int off;
            if (s >= 0 && s < 3) off = (s*64 + x)*64;                 // window elem off
            else                 off = (hwt*Cn + cq*64) | (1 << 30);  // far: global off
            stw[p*JMAX + j] = w;
            sto[p*JMAX + j] = off;
        }
        if (q == 0) atomicMax(snmx, n);
    }
    __syncthreads();

    int nmax = *snmx;
    int c4 = tid & 15;      // float4 group within 64-ch quarter
    int pp = tid >> 4;      // pixel phase 0..15
    float4 a[4];
    #pragma unroll
    for (int u = 0; u < 4; u++) a[u] = make_float4(0.f, 0.f, 0.f, 0.f);

    for (int j = 0; j < nmax; j++) {
        #pragma unroll
        for (int u = 0; u < 4; u++) {
            int p = pp + u*16;
            float w  = stw[p*JMAX + j];
            int  off = sto[p*JMAX + j];
            float4 v;
            if (off & (1 << 30))
                v = *(const float4*)&kb[(off & 0x3FFFFFFF) + c4*4];
            else
                v = *(const float4*)&win[off + c4*4];
            a[u].x += w*v.x; a[u].y += w*v.y; a[u].z += w*v.z; a[u].w += w*v.w;
        }
    }

    #pragma unroll
    for (int u = 0; u < 4; u++) {
        int p = pp + u*16;
        size_t base = ((size_t)(b*HWn + y*Wn + p)) * Cn + cq*64 + c4*4;
        float4 acc = a[u];
        __nv_bfloat16 hx = __float2bfloat16(acc.x);
        __nv_bfloat16 hy = __float2bfloat16(acc.y);
        __nv_bfloat16 hz = __float2bfloat16(acc.z);
        __nv_bfloat16 hw4 = __float2bfloat16(acc.w);
        __nv_bfloat16 lx = __float2bfloat16(acc.x - __bfloat162float(hx));
        __nv_bfloat16 ly = __float2bfloat16(acc.y - __bfloat162float(hy));
        __nv_bfloat16 lz = __float2bfloat16(acc.z - __bfloat162float(hz));
        __nv_bfloat16 lw = __float2bfloat16(acc.w - __bfloat162float(hw4));
        __nv_bfloat162 h0 = __halves2bfloat162(hx, hy);
        __nv_bfloat162 h1 = __halves2bfloat162(hz, hw4);
        __nv_bfloat162 l0 = __halves2bfloat162(lx, ly);
        __nv_bfloat162 l1 = __halves2bfloat162(lz, lw);
        uint2 uh, ul;
        uh.x = *(uint32_t*)&h0; uh.y = *(uint32_t*)&h1;
        ul.x = *(uint32_t*)&l0; ul.y = *(uint32_t*)&l1;
        *(uint2*)&g_sh[base] = uh;
        *(uint2*)&g_sl[base] = ul;
    }
}

// ============================================================
// K5: mma.sync bf16 split GEMM with 3-stage cp.async pipeline
//   D[o,p] = Wh.Sh^T + Wl.Sh^T + Wh.Sl^T  (virtual K = 768)
// ============================================================
#define PITCH_B 80
#define TILE_B  (128*PITCH_B)
#define NCHUNK  24
#define GEMM_SMEM (3*2*TILE_B)

__global__ void __launch_bounds__(256)
k_gemm_mma(const float* __restrict__ bref, float* __restrict__ out) {
    extern __shared__ __align__(16) char gsmg[];
    int tid = threadIdx.x, wid = tid >> 5, lane = tid & 31;
    int p0 = blockIdx.x * 128;
    int o0 = blockIdx.y * 128;
    int bz = blockIdx.z;
    int wr = wid >> 2;
    int wn = wid & 3;

    const __nv_bfloat16* Aseg[3] = {g_wh, g_wl, g_wh};
    const __nv_bfloat16* Bseg[3] = {g_sh, g_sh, g_sl};
    uint32_t sbase = smem_u32(gsmg);

    int rA = tid >> 2;
    int pa = (tid & 3) * 16;

    float acc[4][4][4];
    #pragma unroll
    for (int i = 0; i < 4; i++)
        #pragma unroll
        for (int j = 0; j < 4; j++)
            #pragma unroll
            for (int r = 0; r < 4; r++) acc[i][j][r] = 0.f;

    int lm_row = ((lane >> 3) & 1) * 8 + (lane & 7);
    int lm_col = (lane >> 4) * 16;
    int bn_row = lane >> 2;
    int bn_col = (lane & 3) * 4;

#define ISSUE(CH) do { \
        int _st = (CH) % 3, _seg = (CH) >> 3, _c0 = ((CH) & 7) * 32; \
        const char* _Ag = (const char*)(Aseg[_seg] + (size_t)o0*Cn + _c0) \
                          + (size_t)rA*(Cn*2) + pa; \
        const char* _Bg = (const char*)(Bseg[_seg] + ((size_t)bz*HWn + p0)*Cn + _c0) \
                          + (size_t)rA*(Cn*2) + pa; \
        uint32_t _sa = sbase + _st*(2*TILE_B); \
        uint32_t _sb = _sa + TILE_B; \
        cp16(_sa + rA*PITCH_B + pa,        _Ag); \
        cp16(_sa + (rA+64)*PITCH_B + pa,   _Ag + 64*(Cn*2)); \
        cp16(_sb + rA*PITCH_B + pa,        _Bg); \
        cp16(_sb + (rA+64)*PITCH_B + pa,   _Bg + 64*(Cn*2)); \
        cp_commit(); \
    } while (0)

    ISSUE(0);
    ISSUE(1);

    for (int ch = 0; ch < NCHUNK; ch++) {
        if (ch == NCHUNK - 1) cp_wait<0>(); else cp_wait<1>();
        __syncthreads();
        if (ch + 2 < NCHUNK) ISSUE(ch + 2);

        uint32_t sa = sbase + (ch % 3)*(2*TILE_B);
        uint32_t sb = sa + TILE_B;
        #pragma unroll
        for (int ks = 0; ks < 2; ks++) {
            uint32_t bf[4][2];
            #pragma unroll
            for (int nt = 0; nt < 4; nt++) {
                uint32_t ba = sb + (wn*32 + nt*8 + bn_row)*PITCH_B + bn_col + ks*32;
                bf[nt][0] = lds32(ba);
                bf[nt][1] = lds32(ba + 16);
            }
            #pragma unroll
            for (int mt = 0; mt < 4; mt++) {
                uint32_t a0, a1, a2, a3;
                uint32_t aa = sa + (wr*64 + mt*16 + lm_row)*PITCH_B + lm_col + ks*32;
                ldmatrix_x4(a0, a1, a2, a3, aa);
                #pragma unroll
                for (int nt = 0; nt < 4; nt++)
                    mma16816(acc[mt][nt], a0, a1, a2, a3, bf[nt][0], bf[nt][1]);
            }
        }
    }
#undef ISSUE

    int mrow = lane >> 2;
    int ncol = (lane & 3) * 2;
    #pragma unroll
    for (int mt = 0; mt < 4; mt++) {
        int o = o0 + wr*64 + mt*16 + mrow;
        float bb0 = bref[o], bb1 = bref[o + 8];
        #pragma unroll
        for (int nt = 0; nt < 4; nt++) {
            int p = p0 + wn*32 + nt*8 + ncol;
            float2 gg = *(const float2*)&g_g[bz*HWn + p];
            float2 r0, r1;
            r0.x = acc[mt][nt][0] + bb0*gg.x;
            r0.y = acc[mt][nt][1] + bb0*gg.y;
            r1.x = acc[mt][nt][2] + bb1*gg.x;
            r1.y = acc[mt][nt][3] + bb1*gg.y;
            *(float2*)&out[((size_t)(bz*Cn + o))     * HWn + p] = r0;
            *(float2*)&out[((size_t)(bz*Cn + o + 8)) * HWn + p] = r1;
        }
    }
}

// ============================================================
extern "C" void kernel_launch(void* const* d_in, const int* in_sizes, int n_in,
                              void* d_out, int out_size) {
    const float* query   = (const float*)d_in[0];
    const float* key     = (const float*)d_in[1];
    const float* gmb     = (const float*)d_in[2];
    const float* w_refer = (const float*)d_in[3];
    const float* b_refer = (const float*)d_in[4];
    const float* w_attn  = (const float*)d_in[5];
    const float* b_attn  = (const float*)d_in[6];
    const float* w_mask  = (const float*)d_in[7];
    const float* b_mask  = (const float*)d_in[8];
    const float* w_off   = (const float*)d_in[9];
    const float* b_off   = (const float*)d_in[10];
    const unsigned* temp = (const unsigned*)d_in[11];
    float* out = (float*)d_out;

    static int attr_set = 0;
    if (!attr_set) {
        cudaFuncSetAttribute(k_gemm_mma, cudaFuncAttributeMaxDynamicSharedMemorySize,
                             GEMM_SMEM);
        cudaFuncSetAttribute(k_gather, cudaFuncAttributeMaxDynamicSharedMemorySize,
                             GATHER_SMEM);
        attr_set = 1;
    }

    k_transpose<<<dim3(HWn/32, Cn/32, Bn), dim3(32, 8)>>>(key);
    k_params<<<NPIX/128, 256>>>(query, gmb, b_attn, b_mask, b_off,
                                w_attn, w_mask, w_off, temp);
    k_wsplit<<<Cn*Cn/256, 256>>>(w_refer);
    k_gather<<<dim3(Hn, Bn, 4), 256, GATHER_SMEM>>>();
    k_gemm_mma<<<dim3(HWn/128, Cn/128, Bn), 256, GEMM_SMEM>>>(b_refer, out);
}